// round 1
// baseline (speedup 1.0000x reference)
#include <cuda_runtime.h>

// Dynamic local filtering: out[n,c,h,w] = sum_{k1,k2} x_pad[n,c,h+k1,w+k2] * kern[n,(c*25+k1*5+k2),h,w]
// then leaky_relu(0.2). Replicate padding. Shapes fixed: N=4, C=8, H=W=256, K=5.

#define WID 256
#define HEI 256
#define HW  (WID * HEI)
#define TW  128   // tile width in pixels (32 threads x 4 px)
#define TH  8     // tile height
#define SW  (TW + 4)   // 132, divisible by 4 -> float4-aligned rows
#define SH  (TH + 4)   // 12

__global__ __launch_bounds__(256, 8)
void dynconv5x5_kernel(const float* __restrict__ x,
                       const float* __restrict__ kern,
                       float* __restrict__ out)
{
    __shared__ float tile[SH * SW];

    const int plane = blockIdx.z;           // n*C + c, 0..31
    const int bx = blockIdx.x * TW;
    const int by = blockIdx.y * TH;
    const int tid = threadIdx.y * 32 + threadIdx.x;

    const float* __restrict__ xp = x + (size_t)plane * HW;

    // Cooperative load of x tile with halo; replicate padding via clamp.
    #pragma unroll
    for (int i = tid; i < SH * SW; i += 256) {
        int sy = i / SW;
        int sx = i - sy * SW;
        int gy = by + sy - 2; gy = max(0, min(HEI - 1, gy));
        int gx = bx + sx - 2; gx = max(0, min(WID - 1, gx));
        tile[i] = xp[gy * WID + gx];
    }
    __syncthreads();

    const int lx = threadIdx.x;
    const int ly = threadIdx.y;
    const int w0 = bx + lx * 4;          // first of 4 pixels handled
    const int h  = by + ly;

    // kernel tensor viewed as float4; per tap t the 4 pixels' weights are one LDG.128
    const float4* __restrict__ k4 = (const float4*)kern
        + (size_t)plane * 25 * (HW / 4)
        + (size_t)(h * WID + w0) / 4;

    float ax = 0.f, ay = 0.f, az = 0.f, aw = 0.f;

    #pragma unroll
    for (int dy = 0; dy < 5; dy++) {
        // 8 consecutive x values covering the 4 pixels' horizontal extents
        const float4* srow = (const float4*)&tile[(ly + dy) * SW + lx * 4];
        float4 s0 = srow[0];
        float4 s1 = srow[1];
        float s[8] = { s0.x, s0.y, s0.z, s0.w, s1.x, s1.y, s1.z, s1.w };

        #pragma unroll
        for (int dx = 0; dx < 5; dx++) {
            float4 kv = k4[(size_t)(dy * 5 + dx) * (HW / 4)];
            ax += kv.x * s[dx + 0];
            ay += kv.y * s[dx + 1];
            az += kv.z * s[dx + 2];
            aw += kv.w * s[dx + 3];
        }
    }

    // leaky_relu(0.2)
    ax = ax >= 0.f ? ax : 0.2f * ax;
    ay = ay >= 0.f ? ay : 0.2f * ay;
    az = az >= 0.f ? az : 0.2f * az;
    aw = aw >= 0.f ? aw : 0.2f * aw;

    float4 r = make_float4(ax, ay, az, aw);
    ((float4*)out)[(size_t)plane * (HW / 4) + (size_t)(h * WID + w0) / 4] = r;
}

extern "C" void kernel_launch(void* const* d_in, const int* in_sizes, int n_in,
                              void* d_out, int out_size)
{
    const float* x    = (const float*)d_in[0];   // (4, 8, 256, 256)
    const float* kern = (const float*)d_in[1];   // (4, 200, 256, 256)
    float* out = (float*)d_out;                  // (4, 8, 256, 256)

    dim3 block(32, 8, 1);
    dim3 grid(WID / TW, HEI / TH, 32);           // (2, 32, 32)
    dynconv5x5_kernel<<<grid, block>>>(x, kern, out);
}

// round 2
// speedup vs baseline: 1.1864x; 1.1864x over previous
#include <cuda_runtime.h>

// Dynamic local filtering: out[n,c,h,w] = sum_{k1,k2} x_pad[n,c,h+k1,w+k2] * kern[n,(c*25+k1*5+k2),h,w]
// then leaky_relu(0.2). Replicate padding. Shapes fixed: N=4, C=8, H=W=256, K=5.
// R2: max MLP — preload all 25 weight float4s per thread before the FMA body;
//     streaming cache hints on the 200MB weight read and 8MB output write.

#define WID 256
#define HEI 256
#define HW  (WID * HEI)
#define TW  128   // tile width in pixels (32 threads x 4 px)
#define TH  8     // tile height
#define SW  (TW + 4)   // 132, divisible by 4 -> float4-aligned rows
#define SH  (TH + 4)   // 12

__global__ __launch_bounds__(256)
void dynconv5x5_kernel(const float* __restrict__ x,
                       const float* __restrict__ kern,
                       float* __restrict__ out)
{
    __shared__ float tile[SH * SW];

    const int plane = blockIdx.z;           // n*C + c, 0..31
    const int bx = blockIdx.x * TW;
    const int by = blockIdx.y * TH;
    const int tid = threadIdx.y * 32 + threadIdx.x;

    const int lx = threadIdx.x;
    const int ly = threadIdx.y;
    const int w0 = bx + lx * 4;          // first of 4 pixels handled
    const int h  = by + ly;

    // Weight pointer: per tap t, the 4 pixels' weights are one contiguous float4.
    const float4* __restrict__ k4 = (const float4*)kern
        + (size_t)plane * 25 * (HW / 4)
        + (size_t)(h * WID + w0) / 4;

    // ---- Issue ALL 25 independent LDG.128 weight loads up front (MLP=25). ----
    float4 kv[25];
    #pragma unroll
    for (int t = 0; t < 25; t++) {
        kv[t] = __ldcs(&k4[(size_t)t * (HW / 4)]);
    }

    // Cooperative load of x tile with halo; replicate padding via clamp.
    // (Overlaps with the in-flight weight loads.)
    const float* __restrict__ xp = x + (size_t)plane * HW;
    #pragma unroll
    for (int i = tid; i < SH * SW; i += 256) {
        int sy = i / SW;
        int sx = i - sy * SW;
        int gy = by + sy - 2; gy = max(0, min(HEI - 1, gy));
        int gx = bx + sx - 2; gx = max(0, min(WID - 1, gx));
        tile[i] = xp[gy * WID + gx];
    }
    __syncthreads();

    float ax = 0.f, ay = 0.f, az = 0.f, aw = 0.f;

    #pragma unroll
    for (int dy = 0; dy < 5; dy++) {
        // 8 consecutive x values covering the 4 pixels' horizontal extents
        const float4* srow = (const float4*)&tile[(ly + dy) * SW + lx * 4];
        float4 s0 = srow[0];
        float4 s1 = srow[1];
        float s[8] = { s0.x, s0.y, s0.z, s0.w, s1.x, s1.y, s1.z, s1.w };

        #pragma unroll
        for (int dx = 0; dx < 5; dx++) {
            float4 w = kv[dy * 5 + dx];
            ax += w.x * s[dx + 0];
            ay += w.y * s[dx + 1];
            az += w.z * s[dx + 2];
            aw += w.w * s[dx + 3];
        }
    }

    // leaky_relu(0.2)
    ax = ax >= 0.f ? ax : 0.2f * ax;
    ay = ay >= 0.f ? ay : 0.2f * ay;
    az = az >= 0.f ? az : 0.2f * az;
    aw = aw >= 0.f ? aw : 0.2f * aw;

    float4 r = make_float4(ax, ay, az, aw);
    __stcs(&((float4*)out)[(size_t)plane * (HW / 4) + (size_t)(h * WID + w0) / 4], r);
}

extern "C" void kernel_launch(void* const* d_in, const int* in_sizes, int n_in,
                              void* d_out, int out_size)
{
    const float* x    = (const float*)d_in[0];   // (4, 8, 256, 256)
    const float* kern = (const float*)d_in[1];   // (4, 200, 256, 256)
    float* out = (float*)d_out;                  // (4, 8, 256, 256)

    dim3 block(32, 8, 1);
    dim3 grid(WID / TW, HEI / TH, 32);           // (2, 32, 32)
    dynconv5x5_kernel<<<grid, block>>>(x, kern, out);
}